// round 12
// baseline (speedup 1.0000x reference)
#include <cuda_runtime.h>

#define MAXB   16
#define MAXBLK 256
#define TPB    256
#define MAXM   64

__device__ float g_partC[MAXB * MAXBLK];
__device__ float g_partR[MAXB * MAXBLK];
__device__ int   g_partP[MAXB * MAXBLK];
__device__ unsigned int g_done = 0;

#define NEGK (-0.75f * 0.693147180559945f)  /* -(1-alpha) * ln2 */
#define POSK (-0.25f * 0.693147180559945f)  /* -alpha * ln2     */

template<int KT>
__global__ __launch_bounds__(TPB, 6) void focal_main(
    const float* __restrict__ cls,   // [B, A, K]
    const float* __restrict__ reg,   // [B, A, 4]
    const float* __restrict__ anc,   // [1, A, 4]
    const float* __restrict__ ann,   // [B, M, 5]
    int A, int Kr, int M, int nTiles, int nBlkTotal, float* __restrict__ out)
{
    const int K  = (KT > 0) ? KT : Kr;
    const int K4 = K >> 2;
    const int b   = blockIdx.y;
    const int B   = gridDim.y;
    const int tid = threadIdx.x;

    __shared__ float4 s_box[MAXM];           // x1,y1,x2,y2 (sentinel if padded)
    __shared__ float  s_ga[MAXM];            // gt area
    __shared__ float  s_lab[MAXM];           // label
    __shared__ float  s_w[TPB];
    __shared__ float  s_redC[TPB], s_redR[TPB];
    __shared__ int    s_redP[TPB];
    __shared__ int    s_isLast;
    __shared__ double shC[MAXB], shR[MAXB];

    // ---- load & preprocess GT annotations for this image ----
    if (tid < M && tid < MAXM) {
        const float* g = ann + ((size_t)b * M + tid) * 5;
        float x1 = g[0], y1 = g[1], x2 = g[2], y2 = g[3], lab = g[4];
        if (lab == -1.0f) {                      // padded GT -> zero-overlap sentinel
            x1 = 3.0e37f; x2 = -3.0e37f; y1 = 0.f; y2 = 0.f;
        }
        s_box[tid] = make_float4(x1, y1, x2, y2);
        s_ga[tid]  = (lab == -1.0f) ? 0.f : (x2 - x1) * (y2 - y1);
        s_lab[tid] = lab;
    }
    __syncthreads();

    float accC = 0.f, accR = 0.f;
    int   accP = 0;
    const int mlim = (M < MAXM) ? M : MAXM;

    for (int tile = blockIdx.x; tile < nTiles; tile += gridDim.x) {
        const int a0 = tile * TPB;
        const int a  = a0 + tid;

        // ---- phase 1: branch-free threshold scan (no argmax on hot path) ----
        // p_m = 3*inter - aarea - S_m >= 0  <=>  IoU_m >= 0.5
        // q_m = 3.5*inter - aarea - S_m < 0 <=>  IoU_m < 0.4
        float w = 0.f;
        if (a < A) {
            float4 av = __ldg(((const float4*)anc) + a);
            float aarea = (av.z - av.x) * (av.w - av.y);
            float negA = -aarea;

            float maxp = -3.4e38f, maxq = -3.4e38f;
            #pragma unroll 4
            for (int m = 0; m < mlim; m++) {
                float4 gb = s_box[m];
                float S = s_ga[m];
                float iw = fminf(av.z, gb.z) - fmaxf(av.x, gb.x);
                float ih = fminf(av.w, gb.w) - fmaxf(av.y, gb.y);
                float inter = fmaxf(iw, 0.f) * fmaxf(ih, 0.f);
                float t = fmaf(3.0f, inter, negA);
                float p = t - S;
                float q = fmaf(0.5f, inter, t) - S;
                maxp = fmaxf(maxp, p);
                maxq = fmaxf(maxq, q);
            }

            bool pos = (maxp >= 0.f);
            bool neg = (maxq < 0.f);
            w = (pos || neg) ? NEGK : 0.f;

            if (pos) {
                // rare (~1%): full cross-mult argmax (first-max tie semantics)
                float bi = 0.f, bu = 1.f;
                int   bm = 0;
                for (int m = 0; m < mlim; m++) {
                    float4 gb = s_box[m];
                    float iw = fminf(av.z, gb.z) - fmaxf(av.x, gb.x);
                    float ih = fminf(av.w, gb.w) - fmaxf(av.y, gb.y);
                    float inter = fmaxf(iw, 0.f) * fmaxf(ih, 0.f);
                    float ua = fmaxf(aarea + s_ga[m] - inter, 1e-8f);
                    if (inter * bu > bi * ua) { bi = inter; bu = ua; bm = m; }
                }
                accP++;
                float4 gb = s_box[bm];
                float aw = av.z - av.x;
                float ah = av.w - av.y;
                float gwr = gb.z - gb.x, ghr = gb.w - gb.y;
                float acx = av.x + 0.5f * aw, acy = av.y + 0.5f * ah;
                float gcx = gb.x + 0.5f * gwr, gcy = gb.y + 0.5f * ghr;
                float gw = fmaxf(gwr, 1.f), gh = fmaxf(ghr, 1.f);
                float t0 = ((gcx - acx) / aw) / 0.1f;
                float t1 = ((gcy - acy) / ah) / 0.1f;
                float t2 = logf(gw / aw) / 0.2f;
                float t3 = logf(gh / ah) / 0.2f;
                float4 rv = __ldg(((const float4*)reg) + (size_t)b * A + a);
                float d0 = fabsf(t0 - rv.x);
                float d1 = fabsf(t1 - rv.y);
                float d2 = fabsf(t2 - rv.z);
                float d3 = fabsf(t3 - rv.w);
                const float TH = 1.0f / 9.0f;
                const float CC = 0.5f / 9.0f;
                accR += (d0 <= TH) ? 4.5f * d0 * d0 : d0 - CC;
                accR += (d1 <= TH) ? 4.5f * d1 * d1 : d1 - CC;
                accR += (d2 <= TH) ? 4.5f * d2 * d2 : d2 - CC;
                accR += (d3 <= TH) ? 4.5f * d3 * d3 : d3 - CC;

                // one-hot lane correction: streaming adds NEGK*c^2*lg2(1-c);
                // replace with the positive focal term.
                int lab = (int)s_lab[bm];
                float c = __ldg(cls + ((size_t)b * A + a) * K + lab);
                float u = 1.f - c;
                accC += POSK * u * u * __log2f(c) - NEGK * c * c * __log2f(u);
            }
        }
        s_w[tid] = w;
        __syncthreads();

        // ---- phase 2: branchless coalesced streaming over [a0:a0+256, 0:K] ----
        int nA = A - a0; if (nA > TPB) nA = TPB;
        const float4* cb = (const float4*)(cls + ((size_t)b * A + (size_t)a0) * K);

        if (KT > 0 && nA == TPB) {
            constexpr int ITERS = (KT > 0) ? (KT / 4) : 1;
            #pragma unroll 5
            for (int j = 0; j < ITERS; j++) {
                int i = j * TPB + tid;
                float4 v = __ldcs(cb + i);
                float ww = s_w[i / K4];          // constexpr divisor -> umulhi+shr
                float l0 = __log2f(1.f - v.x);
                float l1 = __log2f(1.f - v.y);
                float l2 = __log2f(1.f - v.z);
                float l3 = __log2f(1.f - v.w);
                float s = fmaf(v.x * v.x, l0,
                          fmaf(v.y * v.y, l1,
                          fmaf(v.z * v.z, l2, (v.w * v.w) * l3)));
                accC = fmaf(ww, s, accC);
            }
        } else {
            int total = nA * K4;
            for (int i = tid; i < total; i += TPB) {
                float4 v = __ldcs(cb + i);
                float ww = s_w[i / K4];
                float l0 = __log2f(1.f - v.x);
                float l1 = __log2f(1.f - v.y);
                float l2 = __log2f(1.f - v.z);
                float l3 = __log2f(1.f - v.w);
                float s = fmaf(v.x * v.x, l0,
                          fmaf(v.y * v.y, l1,
                          fmaf(v.z * v.z, l2, (v.w * v.w) * l3)));
                accC = fmaf(ww, s, accC);
            }
            int kRem = K - (K4 << 2);
            if (kRem) {
                for (int i = tid; i < nA * kRem; i += TPB) {
                    int aL = i / kRem;
                    int k  = (K4 << 2) + (i - aL * kRem);
                    float c = __ldg(cls + ((size_t)b * A + a0 + aL) * K + k);
                    accC = fmaf(s_w[aL], c * c * __log2f(1.f - c), accC);
                }
            }
        }
        __syncthreads();   // protect s_w before next tile rewrites it
    }

    // ---- block reduce & write per-block partials ----
    s_redC[tid] = accC;
    s_redR[tid] = accR;
    s_redP[tid] = accP;
    __syncthreads();
    for (int off = TPB / 2; off > 0; off >>= 1) {
        if (tid < off) {
            s_redC[tid] += s_redC[tid + off];
            s_redR[tid] += s_redR[tid + off];
            s_redP[tid] += s_redP[tid + off];
        }
        __syncthreads();
    }
    if (tid == 0) {
        g_partC[b * MAXBLK + blockIdx.x] = s_redC[0];
        g_partR[b * MAXBLK + blockIdx.x] = s_redR[0];
        g_partP[b * MAXBLK + blockIdx.x] = s_redP[0];
        __threadfence();
        unsigned v = atomicAdd(&g_done, 1u);
        s_isLast = (v == (unsigned)(nBlkTotal - 1));
    }
    __syncthreads();

    // ---- last block: fused finalize (one warp per image) ----
    if (s_isLast) {
        __threadfence();
        const int wrp  = tid >> 5;
        const int lane = tid & 31;
        const int nblk = gridDim.x;
        if (wrp < B) {
            float c = 0.f, r = 0.f; int p = 0;
            for (int i = lane; i < nblk; i += 32) {
                c += g_partC[wrp * MAXBLK + i];
                r += g_partR[wrp * MAXBLK + i];
                p += g_partP[wrp * MAXBLK + i];
            }
            #pragma unroll
            for (int off = 16; off > 0; off >>= 1) {
                c += __shfl_down_sync(0xffffffffu, c, off);
                r += __shfl_down_sync(0xffffffffu, r, off);
                p += __shfl_down_sync(0xffffffffu, p, off);
            }
            bool hv = false;
            for (int m = lane; m < M; m += 32)
                if (__ldg(ann + ((size_t)wrp * M + m) * 5 + 4) != -1.0f) hv = true;
            unsigned hvb = __ballot_sync(0xffffffffu, hv);
            if (lane == 0) {
                double cv = 0.0, rv = 0.0;
                if (hvb != 0u) cv = (double)c / (double)(p > 1 ? p : 1);
                if (p > 0) {
                    int d = p * 4 > 1 ? p * 4 : 1;
                    rv = (double)r / (double)d;
                }
                shC[wrp] = cv;
                shR[wrp] = rv;
            }
        }
        __syncthreads();
        if (tid == 0) {
            double cs = 0.0, rs = 0.0;
            for (int i = 0; i < B; i++) { cs += shC[i]; rs += shR[i]; }
            out[0] = (float)(cs / (double)B);
            out[1] = (float)(rs / (double)B);
            atomicExch(&g_done, 0u);   // reset for graph replay
        }
    }
}

extern "C" void kernel_launch(void* const* d_in, const int* in_sizes, int n_in,
                              void* d_out, int out_size) {
    const float* cls = (const float*)d_in[0];
    const float* reg = (const float*)d_in[1];
    const float* anc = (const float*)d_in[2];
    const float* ann = (const float*)d_in[3];

    int A = in_sizes[2] / 4;                                        // anchors [1,A,4]
    int B = in_sizes[1] / (A * 4);                                  // regressions [B,A,4]
    int K = (int)((long long)in_sizes[0] / ((long long)A * B));     // cls [B,A,K]
    int M = in_sizes[3] / (B * 5);                                  // annotations [B,M,5]

    int nTiles = (A + TPB - 1) / TPB;
    int gx0 = (148 * 6) / (B > 0 ? B : 1);      // round-6 grid: 6 blocks/SM target
    if (gx0 < 1) gx0 = 1;
    int tpb = (nTiles + gx0 - 1) / gx0;         // balanced tiles per block
    int gx  = (nTiles + tpb - 1) / tpb;
    if (gx > MAXBLK) gx = MAXBLK;
    if (gx < 1) gx = 1;
    dim3 grid(gx, B);

    if (K == 80)
        focal_main<80><<<grid, TPB>>>(cls, reg, anc, ann, A, K, M, nTiles, gx * B, (float*)d_out);
    else
        focal_main<0><<<grid, TPB>>>(cls, reg, anc, ann, A, K, M, nTiles, gx * B, (float*)d_out);
}

// round 13
// speedup vs baseline: 1.0673x; 1.0673x over previous
#include <cuda_runtime.h>
#include <cstdint>

#define MAXB   16
#define MAXBLK 256
#define TPB    256
#define MAXM   64
#define MAXT   8     /* max tiles (slots) per block */

__device__ float g_partC[MAXB * MAXBLK];
__device__ float g_partR[MAXB * MAXBLK];
__device__ int   g_partP[MAXB * MAXBLK];
__device__ unsigned int g_done = 0;

#define NEGK (-0.75f * 0.693147180559945f)  /* -(1-alpha) * ln2 */
#define POSK (-0.25f * 0.693147180559945f)  /* -alpha * ln2     */

__device__ __forceinline__ uint32_t smem_u32(const void* p) {
    uint32_t a;
    asm("{ .reg .u64 t; cvta.to.shared.u64 t, %1; cvt.u32.u64 %0, t; }"
        : "=r"(a) : "l"(p));
    return a;
}

#define MBAR_INIT(addr, count) \
    asm volatile("mbarrier.init.shared.b64 [%0], %1;" :: "r"(addr), "r"(count) : "memory")
#define MBAR_ARRIVE(addr) \
    asm volatile("mbarrier.arrive.shared.b64 _, [%0];" :: "r"(addr) : "memory")

#define MBAR_WAIT_PARITY(mbar_smem_addr, phase_parity) do { \
    uint32_t _mbar = (uint32_t)(mbar_smem_addr); \
    uint32_t _parity = (uint32_t)(phase_parity); \
    uint32_t _done; \
    asm volatile( \
        "{\n\t" \
        ".reg .pred p;\n\t" \
        "mbarrier.try_wait.parity.acquire.cta.shared::cta.b64 p, [%1], %2;\n\t" \
        "selp.b32 %0, 1, 0, p;\n\t" \
        "}" \
        : "=r"(_done) : "r"(_mbar), "r"(_parity) : "memory"); \
    if (!_done) { \
        asm volatile( \
            "{\n\t" \
            ".reg .pred P1;\n\t" \
            "WAIT_LOOP_%=:\n\t" \
            "mbarrier.try_wait.parity.acquire.cta.shared::cta.b64 P1, [%0], %1, 0x989680;\n\t" \
            "@P1 bra.uni WAIT_DONE_%=;\n\t" \
            "bra.uni WAIT_LOOP_%=;\n\t" \
            "WAIT_DONE_%=:\n\t" \
            "}" \
            :: "r"(_mbar), "r"(_parity) : "memory"); \
    } \
} while(0)

template<int KT>
__global__ __launch_bounds__(TPB, 6) void focal_main(
    const float* __restrict__ cls,   // [B, A, K]
    const float* __restrict__ reg,   // [B, A, 4]
    const float* __restrict__ anc,   // [1, A, 4]
    const float* __restrict__ ann,   // [B, M, 5]
    int A, int Kr, int M, int nTiles, int nBlkTotal, float* __restrict__ out)
{
    const int K  = (KT > 0) ? KT : Kr;
    const int K4 = K >> 2;
    const int b   = blockIdx.y;
    const int B   = gridDim.y;
    const int tid = threadIdx.x;

    __shared__ float4 s_box[MAXM];            // x1,y1,x2,y2 (sentinel if padded)
    __shared__ float2 s_meta[MAXM];           // area, label
    __shared__ float  s_w[MAXT * TPB];        // weight slots, one per local tile
    __shared__ unsigned long long s_full[MAXT];  // one-shot mbarriers
    __shared__ float  s_redC[TPB], s_redR[TPB];
    __shared__ int    s_redP[TPB];
    __shared__ int    s_isLast;
    __shared__ double shC[MAXB], shR[MAXB];

    // ---- load & preprocess GT annotations for this image ----
    if (tid < M && tid < MAXM) {
        const float* g = ann + ((size_t)b * M + tid) * 5;
        float x1 = g[0], y1 = g[1], x2 = g[2], y2 = g[3], lab = g[4];
        if (lab == -1.0f) {                      // padded GT -> zero-overlap sentinel
            x1 = 3.0e37f; x2 = -3.0e37f; y1 = 0.f; y2 = 0.f;
        }
        s_box[tid]  = make_float4(x1, y1, x2, y2);
        s_meta[tid] = make_float2((lab == -1.0f) ? 0.f : (x2 - x1) * (y2 - y1), lab);
    }
    if (tid == 0) {
        #pragma unroll
        for (int s = 0; s < MAXT; s++) MBAR_INIT(smem_u32(&s_full[s]), 128);
    }
    __syncthreads();

    float accC = 0.f, accR = 0.f;
    int   accP = 0;
    const int mlim = (M < MAXM) ? M : MAXM;

    if (tid >= 128) {
        // ================= PRODUCER warps (4-7): phase-1 IoU / reg loss =================
        const int ptid = tid - 128;
        int lt = 0;
        for (int tile = blockIdx.x; tile < nTiles; tile += gridDim.x, lt++) {
            const int a0 = tile * TPB;
            #pragma unroll
            for (int half = 0; half < 2; half++) {
                const int a = a0 + half * 128 + ptid;
                float w = 0.f;
                if (a < A) {
                    float4 av = __ldg(((const float4*)anc) + a);
                    float aarea = (av.z - av.x) * (av.w - av.y);

                    // best IoU as (inter, ua) pair; strict > keeps first-argmax ties
                    float bi = 0.f, bu = 1.f;
                    int   bm = -1;
                    #pragma unroll 4
                    for (int m = 0; m < mlim; m++) {
                        float4 gb = s_box[m];
                        float2 gm = s_meta[m];
                        float iw = fminf(av.z, gb.z) - fmaxf(av.x, gb.x);
                        float ih = fminf(av.w, gb.w) - fmaxf(av.y, gb.y);
                        float inter = fmaxf(iw, 0.f) * fmaxf(ih, 0.f);
                        float ua = fmaxf(aarea + gm.x - inter, 1e-8f);
                        if (inter * bu > bi * ua) { bi = inter; bu = ua; bm = m; }
                    }

                    bool pos = (bm >= 0) && (bi >= 0.5f * bu);
                    bool neg = (bi < 0.4f * bu);
                    w = (pos || neg) ? NEGK : 0.f;

                    if (pos) {
                        accP++;
                        float4 gb = s_box[bm];
                        float aw = av.z - av.x;
                        float ah = av.w - av.y;
                        float gwr = gb.z - gb.x, ghr = gb.w - gb.y;
                        float acx = av.x + 0.5f * aw, acy = av.y + 0.5f * ah;
                        float gcx = gb.x + 0.5f * gwr, gcy = gb.y + 0.5f * ghr;
                        float gw = fmaxf(gwr, 1.f), gh = fmaxf(ghr, 1.f);
                        float t0 = ((gcx - acx) / aw) / 0.1f;
                        float t1 = ((gcy - acy) / ah) / 0.1f;
                        float t2 = logf(gw / aw) / 0.2f;
                        float t3 = logf(gh / ah) / 0.2f;
                        float4 rv = __ldg(((const float4*)reg) + (size_t)b * A + a);
                        float d0 = fabsf(t0 - rv.x);
                        float d1 = fabsf(t1 - rv.y);
                        float d2 = fabsf(t2 - rv.z);
                        float d3 = fabsf(t3 - rv.w);
                        const float TH = 1.0f / 9.0f;
                        const float CC = 0.5f / 9.0f;
                        accR += (d0 <= TH) ? 4.5f * d0 * d0 : d0 - CC;
                        accR += (d1 <= TH) ? 4.5f * d1 * d1 : d1 - CC;
                        accR += (d2 <= TH) ? 4.5f * d2 * d2 : d2 - CC;
                        accR += (d3 <= TH) ? 4.5f * d3 * d3 : d3 - CC;

                        // one-hot lane correction: streaming adds NEGK*c^2*lg2(1-c);
                        // replace with the positive focal term.
                        int lab = (int)s_meta[bm].y;
                        float c = __ldg(cls + ((size_t)b * A + a) * K + lab);
                        float u = 1.f - c;
                        accC += POSK * u * u * __log2f(c) - NEGK * c * c * __log2f(u);
                    }
                }
                s_w[lt * TPB + half * 128 + ptid] = w;
            }
            MBAR_ARRIVE(smem_u32(&s_full[lt]));   // release: slot lt ready
        }
    } else {
        // ================= CONSUMER warps (0-3): phase-2 streaming =================
        int lt = 0;
        for (int tile = blockIdx.x; tile < nTiles; tile += gridDim.x, lt++) {
            const int a0 = tile * TPB;
            int nA = A - a0; if (nA > TPB) nA = TPB;
            MBAR_WAIT_PARITY(smem_u32(&s_full[lt]), 0);   // acquire slot lt

            const float4* cb = (const float4*)(cls + ((size_t)b * A + (size_t)a0) * K);
            const float*  wr = s_w + lt * TPB;

            if (KT > 0 && nA == TPB) {
                constexpr int ITERS = (KT > 0) ? (KT / 4 * 2) : 1;   // 5120/128 = 40
                #pragma unroll 4
                for (int j = 0; j < ITERS; j++) {
                    int i = j * 128 + tid;
                    float4 v = __ldcs(cb + i);
                    float ww = wr[i / K4];        // constexpr divisor -> umulhi+shr
                    float l0 = __log2f(1.f - v.x);
                    float l1 = __log2f(1.f - v.y);
                    float l2 = __log2f(1.f - v.z);
                    float l3 = __log2f(1.f - v.w);
                    float s = fmaf(v.x * v.x, l0,
                              fmaf(v.y * v.y, l1,
                              fmaf(v.z * v.z, l2, (v.w * v.w) * l3)));
                    accC = fmaf(ww, s, accC);
                }
            } else {
                int total = nA * K4;
                for (int i = tid; i < total; i += 128) {
                    float4 v = __ldcs(cb + i);
                    float ww = wr[i / K4];
                    float l0 = __log2f(1.f - v.x);
                    float l1 = __log2f(1.f - v.y);
                    float l2 = __log2f(1.f - v.z);
                    float l3 = __log2f(1.f - v.w);
                    float s = fmaf(v.x * v.x, l0,
                              fmaf(v.y * v.y, l1,
                              fmaf(v.z * v.z, l2, (v.w * v.w) * l3)));
                    accC = fmaf(ww, s, accC);
                }
                int kRem = K - (K4 << 2);
                if (kRem) {
                    for (int i = tid; i < nA * kRem; i += 128) {
                        int aL = i / kRem;
                        int k  = (K4 << 2) + (i - aL * kRem);
                        float c = __ldg(cls + ((size_t)b * A + a0 + aL) * K + k);
                        accC = fmaf(wr[aL], c * c * __log2f(1.f - c), accC);
                    }
                }
            }
        }
    }
    __syncthreads();   // join producer/consumer roles

    // ---- block reduce & write per-block partials ----
    s_redC[tid] = accC;
    s_redR[tid] = accR;
    s_redP[tid] = accP;
    __syncthreads();
    for (int off = TPB / 2; off > 0; off >>= 1) {
        if (tid < off) {
            s_redC[tid] += s_redC[tid + off];
            s_redR[tid] += s_redR[tid + off];
            s_redP[tid] += s_redP[tid + off];
        }
        __syncthreads();
    }
    if (tid == 0) {
        g_partC[b * MAXBLK + blockIdx.x] = s_redC[0];
        g_partR[b * MAXBLK + blockIdx.x] = s_redR[0];
        g_partP[b * MAXBLK + blockIdx.x] = s_redP[0];
        __threadfence();
        unsigned v = atomicAdd(&g_done, 1u);
        s_isLast = (v == (unsigned)(nBlkTotal - 1));
    }
    __syncthreads();

    // ---- last block: fused finalize (one warp per image) ----
    if (s_isLast) {
        __threadfence();
        const int wrp  = tid >> 5;
        const int lane = tid & 31;
        const int nblk = gridDim.x;
        if (wrp < B) {
            float c = 0.f, r = 0.f; int p = 0;
            for (int i = lane; i < nblk; i += 32) {
                c += g_partC[wrp * MAXBLK + i];
                r += g_partR[wrp * MAXBLK + i];
                p += g_partP[wrp * MAXBLK + i];
            }
            #pragma unroll
            for (int off = 16; off > 0; off >>= 1) {
                c += __shfl_down_sync(0xffffffffu, c, off);
                r += __shfl_down_sync(0xffffffffu, r, off);
                p += __shfl_down_sync(0xffffffffu, p, off);
            }
            bool hv = false;
            for (int m = lane; m < M; m += 32)
                if (__ldg(ann + ((size_t)wrp * M + m) * 5 + 4) != -1.0f) hv = true;
            unsigned hvb = __ballot_sync(0xffffffffu, hv);
            if (lane == 0) {
                double cv = 0.0, rv = 0.0;
                if (hvb != 0u) cv = (double)c / (double)(p > 1 ? p : 1);
                if (p > 0) {
                    int d = p * 4 > 1 ? p * 4 : 1;
                    rv = (double)r / (double)d;
                }
                shC[wrp] = cv;
                shR[wrp] = rv;
            }
        }
        __syncthreads();
        if (tid == 0) {
            double cs = 0.0, rs = 0.0;
            for (int i = 0; i < B; i++) { cs += shC[i]; rs += shR[i]; }
            out[0] = (float)(cs / (double)B);
            out[1] = (float)(rs / (double)B);
            atomicExch(&g_done, 0u);   // reset for graph replay
        }
    }
}

extern "C" void kernel_launch(void* const* d_in, const int* in_sizes, int n_in,
                              void* d_out, int out_size) {
    const float* cls = (const float*)d_in[0];
    const float* reg = (const float*)d_in[1];
    const float* anc = (const float*)d_in[2];
    const float* ann = (const float*)d_in[3];

    int A = in_sizes[2] / 4;                                        // anchors [1,A,4]
    int B = in_sizes[1] / (A * 4);                                  // regressions [B,A,4]
    int K = (int)((long long)in_sizes[0] / ((long long)A * B));     // cls [B,A,K]
    int M = in_sizes[3] / (B * 5);                                  // annotations [B,M,5]

    int nTiles = (A + TPB - 1) / TPB;
    int gx0 = (148 * 6) / (B > 0 ? B : 1);      // round-6 grid: 6 blocks/SM target
    if (gx0 < 1) gx0 = 1;
    int tpb = (nTiles + gx0 - 1) / gx0;         // balanced tiles per block
    if (tpb > MAXT) tpb = MAXT;                 // cap slots (extra waves are safe)
    int gx  = (nTiles + tpb - 1) / tpb;
    if (gx > MAXBLK) gx = MAXBLK;
    if (gx < 1) gx = 1;
    // ensure per-block tile count fits MAXT slots
    while ((nTiles + gx - 1) / gx > MAXT && gx < MAXBLK) gx++;
    dim3 grid(gx, B);

    if (K == 80)
        focal_main<80><<<grid, TPB>>>(cls, reg, anc, ann, A, K, M, nTiles, gx * B, (float*)d_out);
    else
        focal_main<0><<<grid, TPB>>>(cls, reg, anc, ann, A, K, M, nTiles, gx * B, (float*)d_out);
}

// round 14
// speedup vs baseline: 1.1428x; 1.0708x over previous
#include <cuda_runtime.h>

#define MAXB   16
#define MAXBLK 256
#define TPB    256
#define MAXM   64

__device__ float g_partC[MAXB * MAXBLK];
__device__ float g_partR[MAXB * MAXBLK];
__device__ int   g_partP[MAXB * MAXBLK];
__device__ unsigned int g_done = 0;

#define NEGK (-0.75f * 0.693147180559945f)  /* -(1-alpha) * ln2 */
#define POSK (-0.25f * 0.693147180559945f)  /* -alpha * ln2     */

// Phase 1 for one anchor: IoU argmax vs GTs in smem -> weight; accumulates
// reg-loss / pos-count / one-hot cls correction. Byte-identical math to round 6.
template<int KT>
__device__ __forceinline__ float phase1_anchor(
    int a, int A, int K, int mlim, int b,
    const float* __restrict__ cls, const float* __restrict__ reg,
    const float* __restrict__ anc,
    const float4* s_box, const float2* s_meta,
    float& accC, float& accR, int& accP)
{
    float w = 0.f;
    if (a < A) {
        float4 av = __ldg(((const float4*)anc) + a);
        float aarea = (av.z - av.x) * (av.w - av.y);

        // best IoU as (inter, ua) pair; strict > keeps first-argmax tie semantics
        float bi = 0.f, bu = 1.f;
        int   bm = -1;
        #pragma unroll 4
        for (int m = 0; m < mlim; m++) {
            float4 gb = s_box[m];
            float2 gm = s_meta[m];
            float iw = fminf(av.z, gb.z) - fmaxf(av.x, gb.x);
            float ih = fminf(av.w, gb.w) - fmaxf(av.y, gb.y);
            float inter = fmaxf(iw, 0.f) * fmaxf(ih, 0.f);
            float ua = fmaxf(aarea + gm.x - inter, 1e-8f);
            if (inter * bu > bi * ua) { bi = inter; bu = ua; bm = m; }
        }

        bool pos = (bm >= 0) && (bi >= 0.5f * bu);
        bool neg = (bi < 0.4f * bu);
        w = (pos || neg) ? NEGK : 0.f;

        if (pos) {
            accP++;
            float4 gb = s_box[bm];
            float aw = av.z - av.x;
            float ah = av.w - av.y;
            float gwr = gb.z - gb.x, ghr = gb.w - gb.y;
            float acx = av.x + 0.5f * aw, acy = av.y + 0.5f * ah;
            float gcx = gb.x + 0.5f * gwr, gcy = gb.y + 0.5f * ghr;
            float gw = fmaxf(gwr, 1.f), gh = fmaxf(ghr, 1.f);
            float t0 = ((gcx - acx) / aw) / 0.1f;
            float t1 = ((gcy - acy) / ah) / 0.1f;
            float t2 = logf(gw / aw) / 0.2f;
            float t3 = logf(gh / ah) / 0.2f;
            float4 rv = __ldg(((const float4*)reg) + (size_t)b * A + a);
            float d0 = fabsf(t0 - rv.x);
            float d1 = fabsf(t1 - rv.y);
            float d2 = fabsf(t2 - rv.z);
            float d3 = fabsf(t3 - rv.w);
            const float TH = 1.0f / 9.0f;
            const float CC = 0.5f / 9.0f;
            accR += (d0 <= TH) ? 4.5f * d0 * d0 : d0 - CC;
            accR += (d1 <= TH) ? 4.5f * d1 * d1 : d1 - CC;
            accR += (d2 <= TH) ? 4.5f * d2 * d2 : d2 - CC;
            accR += (d3 <= TH) ? 4.5f * d3 * d3 : d3 - CC;

            // one-hot lane correction: streaming adds NEGK*c^2*lg2(1-c);
            // replace with the positive focal term.
            int lab = (int)s_meta[bm].y;
            float c = __ldg(cls + ((size_t)b * A + a) * K + lab);
            float u = 1.f - c;
            accC += POSK * u * u * __log2f(c) - NEGK * c * c * __log2f(u);
        }
    }
    return w;
}

template<int KT>
__global__ __launch_bounds__(TPB, 6) void focal_main(
    const float* __restrict__ cls,   // [B, A, K]
    const float* __restrict__ reg,   // [B, A, 4]
    const float* __restrict__ anc,   // [1, A, 4]
    const float* __restrict__ ann,   // [B, M, 5]
    int A, int Kr, int M, int nTiles, int nBlkTotal, float* __restrict__ out)
{
    const int K  = (KT > 0) ? KT : Kr;
    const int K4 = K >> 2;
    const int b   = blockIdx.y;
    const int B   = gridDim.y;
    const int tid = threadIdx.x;

    __shared__ float4 s_box[MAXM];           // x1,y1,x2,y2 (sentinel if padded)
    __shared__ float2 s_meta[MAXM];          // area, label
    __shared__ float  s_w[2][TPB];           // double-buffered weights
    __shared__ float  s_redC[TPB], s_redR[TPB];
    __shared__ int    s_redP[TPB];
    __shared__ int    s_isLast;
    __shared__ double shC[MAXB], shR[MAXB];

    // ---- load & preprocess GT annotations for this image ----
    if (tid < M && tid < MAXM) {
        const float* g = ann + ((size_t)b * M + tid) * 5;
        float x1 = g[0], y1 = g[1], x2 = g[2], y2 = g[3], lab = g[4];
        if (lab == -1.0f) {                      // padded GT -> zero-overlap sentinel
            x1 = 3.0e37f; x2 = -3.0e37f; y1 = 0.f; y2 = 0.f;
        }
        s_box[tid]  = make_float4(x1, y1, x2, y2);
        s_meta[tid] = make_float2((lab == -1.0f) ? 0.f : (x2 - x1) * (y2 - y1), lab);
    }
    __syncthreads();

    float accC = 0.f, accR = 0.f;
    int   accP = 0;
    const int mlim = (M < MAXM) ? M : MAXM;

    // ---- software-pipelined tile loop: one barrier per tile ----
    // prologue: phase 1 for this block's first tile
    float w = phase1_anchor<KT>(blockIdx.x * TPB + tid, A, K, mlim, b,
                                cls, reg, anc, s_box, s_meta, accC, accR, accP);
    int buf = 0;

    for (int tile = blockIdx.x; tile < nTiles; tile += gridDim.x) {
        const int a0 = tile * TPB;

        s_w[buf][tid] = w;
        __syncthreads();   // publish weights; also protects buffer rotation

        // ---- phase 2: branchless coalesced streaming over [a0:a0+nA, 0:K] ----
        int nA = A - a0; if (nA > TPB) nA = TPB;
        const float4* cb = (const float4*)(cls + ((size_t)b * A + (size_t)a0) * K);
        const float*  wr = s_w[buf];

        if (KT > 0 && nA == TPB) {
            constexpr int ITERS = (KT > 0) ? (KT / 4) : 1;
            #pragma unroll 5
            for (int j = 0; j < ITERS; j++) {
                int i = j * TPB + tid;
                float4 v = __ldcs(cb + i);
                float ww = wr[i / K4];           // constexpr divisor -> umulhi+shr
                float l0 = __log2f(1.f - v.x);
                float l1 = __log2f(1.f - v.y);
                float l2 = __log2f(1.f - v.z);
                float l3 = __log2f(1.f - v.w);
                float s = fmaf(v.x * v.x, l0,
                          fmaf(v.y * v.y, l1,
                          fmaf(v.z * v.z, l2, (v.w * v.w) * l3)));
                accC = fmaf(ww, s, accC);
            }
        } else {
            int total = nA * K4;
            for (int i = tid; i < total; i += TPB) {
                float4 v = __ldcs(cb + i);
                float ww = wr[i / K4];
                float l0 = __log2f(1.f - v.x);
                float l1 = __log2f(1.f - v.y);
                float l2 = __log2f(1.f - v.z);
                float l3 = __log2f(1.f - v.w);
                float s = fmaf(v.x * v.x, l0,
                          fmaf(v.y * v.y, l1,
                          fmaf(v.z * v.z, l2, (v.w * v.w) * l3)));
                accC = fmaf(ww, s, accC);
            }
            int kRem = K - (K4 << 2);
            if (kRem) {
                for (int i = tid; i < nA * kRem; i += TPB) {
                    int aL = i / kRem;
                    int k  = (K4 << 2) + (i - aL * kRem);
                    float c = __ldg(cls + ((size_t)b * A + a0 + aL) * K + k);
                    accC = fmaf(wr[aL], c * c * __log2f(1.f - c), accC);
                }
            }
        }

        // ---- phase 1 for the NEXT tile: issues while streaming loads drain ----
        int nextTile = tile + gridDim.x;
        if (nextTile < nTiles) {
            w = phase1_anchor<KT>(nextTile * TPB + tid, A, K, mlim, b,
                                  cls, reg, anc, s_box, s_meta, accC, accR, accP);
        }
        buf ^= 1;
    }

    // ---- block reduce & write per-block partials ----
    s_redC[tid] = accC;
    s_redR[tid] = accR;
    s_redP[tid] = accP;
    __syncthreads();
    for (int off = TPB / 2; off > 0; off >>= 1) {
        if (tid < off) {
            s_redC[tid] += s_redC[tid + off];
            s_redR[tid] += s_redR[tid + off];
            s_redP[tid] += s_redP[tid + off];
        }
        __syncthreads();
    }
    if (tid == 0) {
        g_partC[b * MAXBLK + blockIdx.x] = s_redC[0];
        g_partR[b * MAXBLK + blockIdx.x] = s_redR[0];
        g_partP[b * MAXBLK + blockIdx.x] = s_redP[0];
        __threadfence();
        unsigned v = atomicAdd(&g_done, 1u);
        s_isLast = (v == (unsigned)(nBlkTotal - 1));
    }
    __syncthreads();

    // ---- last block: fused finalize (one warp per image) ----
    if (s_isLast) {
        __threadfence();
        const int wrp  = tid >> 5;
        const int lane = tid & 31;
        const int nblk = gridDim.x;
        if (wrp < B) {
            float c = 0.f, r = 0.f; int p = 0;
            for (int i = lane; i < nblk; i += 32) {
                c += g_partC[wrp * MAXBLK + i];
                r += g_partR[wrp * MAXBLK + i];
                p += g_partP[wrp * MAXBLK + i];
            }
            #pragma unroll
            for (int off = 16; off > 0; off >>= 1) {
                c += __shfl_down_sync(0xffffffffu, c, off);
                r += __shfl_down_sync(0xffffffffu, r, off);
                p += __shfl_down_sync(0xffffffffu, p, off);
            }
            bool hv = false;
            for (int m = lane; m < M; m += 32)
                if (__ldg(ann + ((size_t)wrp * M + m) * 5 + 4) != -1.0f) hv = true;
            unsigned hvb = __ballot_sync(0xffffffffu, hv);
            if (lane == 0) {
                double cv = 0.0, rv = 0.0;
                if (hvb != 0u) cv = (double)c / (double)(p > 1 ? p : 1);
                if (p > 0) {
                    int d = p * 4 > 1 ? p * 4 : 1;
                    rv = (double)r / (double)d;
                }
                shC[wrp] = cv;
                shR[wrp] = rv;
            }
        }
        __syncthreads();
        if (tid == 0) {
            double cs = 0.0, rs = 0.0;
            for (int i = 0; i < B; i++) { cs += shC[i]; rs += shR[i]; }
            out[0] = (float)(cs / (double)B);
            out[1] = (float)(rs / (double)B);
            atomicExch(&g_done, 0u);   // reset for graph replay
        }
    }
}

extern "C" void kernel_launch(void* const* d_in, const int* in_sizes, int n_in,
                              void* d_out, int out_size) {
    const float* cls = (const float*)d_in[0];
    const float* reg = (const float*)d_in[1];
    const float* anc = (const float*)d_in[2];
    const float* ann = (const float*)d_in[3];

    int A = in_sizes[2] / 4;                                        // anchors [1,A,4]
    int B = in_sizes[1] / (A * 4);                                  // regressions [B,A,4]
    int K = (int)((long long)in_sizes[0] / ((long long)A * B));     // cls [B,A,K]
    int M = in_sizes[3] / (B * 5);                                  // annotations [B,M,5]

    int nTiles = (A + TPB - 1) / TPB;
    int gx0 = (148 * 6) / (B > 0 ? B : 1);      // round-6 grid: 6 blocks/SM target
    if (gx0 < 1) gx0 = 1;
    int tpb = (nTiles + gx0 - 1) / gx0;         // balanced tiles per block
    int gx  = (nTiles + tpb - 1) / tpb;
    if (gx > MAXBLK) gx = MAXBLK;
    if (gx < 1) gx = 1;
    dim3 grid(gx, B);

    if (K == 80)
        focal_main<80><<<grid, TPB>>>(cls, reg, anc, ann, A, K, M, nTiles, gx * B, (float*)d_out);
    else
        focal_main<0><<<grid, TPB>>>(cls, reg, anc, ann, A, K, M, nTiles, gx * B, (float*)d_out);
}

// round 15
// speedup vs baseline: 1.1813x; 1.0337x over previous
#include <cuda_runtime.h>

#define MAXB   16
#define MAXBLK 256
#define TPB    256
#define MAXM   64

__device__ float g_partC[MAXB * MAXBLK];
__device__ float g_partR[MAXB * MAXBLK];
__device__ int   g_partP[MAXB * MAXBLK];
__device__ unsigned int g_done = 0;

#define NEGK (-0.75f * 0.693147180559945f)  /* -(1-alpha) * ln2 */
#define POSK (-0.25f * 0.693147180559945f)  /* -alpha * ln2     */

// ---- packed f32x2 helpers (sm_103a) ----
__device__ __forceinline__ unsigned long long pk2(float lo, float hi) {
    unsigned long long r;
    asm("mov.b64 %0, {%1, %2};" : "=l"(r) : "f"(lo), "f"(hi));
    return r;
}
__device__ __forceinline__ void upk2(unsigned long long v, float& lo, float& hi) {
    asm("mov.b64 {%0, %1}, %2;" : "=f"(lo), "=f"(hi) : "l"(v));
}
__device__ __forceinline__ unsigned long long mul2(unsigned long long a, unsigned long long b) {
    unsigned long long d;
    asm("mul.rn.f32x2 %0, %1, %2;" : "=l"(d) : "l"(a), "l"(b));
    return d;
}
__device__ __forceinline__ unsigned long long add2(unsigned long long a, unsigned long long b) {
    unsigned long long d;
    asm("add.rn.f32x2 %0, %1, %2;" : "=l"(d) : "l"(a), "l"(b));
    return d;
}
__device__ __forceinline__ unsigned long long fma2(unsigned long long a, unsigned long long b,
                                                   unsigned long long c) {
    unsigned long long d;
    asm("fma.rn.f32x2 %0, %1, %2, %3;" : "=l"(d) : "l"(a), "l"(b), "l"(c));
    return d;
}

template<int KT>
__global__ __launch_bounds__(TPB, 6) void focal_main(
    const float* __restrict__ cls,   // [B, A, K]
    const float* __restrict__ reg,   // [B, A, 4]
    const float* __restrict__ anc,   // [1, A, 4]
    const float* __restrict__ ann,   // [B, M, 5]
    int A, int Kr, int M, int nTiles, int nBlkTotal, float* __restrict__ out)
{
    const int K  = (KT > 0) ? KT : Kr;
    const int K4 = K >> 2;
    const int b   = blockIdx.y;
    const int B   = gridDim.y;
    const int tid = threadIdx.x;

    __shared__ float4 s_box[MAXM];           // x1,y1,x2,y2 (sentinel if padded)
    __shared__ float2 s_meta[MAXM];          // area, label
    __shared__ float  s_w[TPB];
    __shared__ float  s_redC[TPB], s_redR[TPB];
    __shared__ int    s_redP[TPB];
    __shared__ int    s_isLast;
    __shared__ double shC[MAXB], shR[MAXB];

    // ---- load & preprocess GT annotations for this image ----
    if (tid < M && tid < MAXM) {
        const float* g = ann + ((size_t)b * M + tid) * 5;
        float x1 = g[0], y1 = g[1], x2 = g[2], y2 = g[3], lab = g[4];
        if (lab == -1.0f) {                      // padded GT -> zero-overlap sentinel
            x1 = 3.0e37f; x2 = -3.0e37f; y1 = 0.f; y2 = 0.f;
        }
        s_box[tid]  = make_float4(x1, y1, x2, y2);
        s_meta[tid] = make_float2((lab == -1.0f) ? 0.f : (x2 - x1) * (y2 - y1), lab);
    }
    __syncthreads();

    float accC = 0.f, accR = 0.f;
    int   accP = 0;
    const int mlim = (M < MAXM) ? M : MAXM;
    const unsigned long long ONE2 = pk2(1.f, 1.f);
    const unsigned long long NEG2 = pk2(-1.f, -1.f);

    for (int tile = blockIdx.x; tile < nTiles; tile += gridDim.x) {
        const int a0 = tile * TPB;
        const int a  = a0 + tid;

        // ---- phase 1: per-anchor IoU argmax -> weight, reg loss, pos correction ----
        float w = 0.f;
        if (a < A) {
            float4 av = __ldg(((const float4*)anc) + a);
            float aarea = (av.z - av.x) * (av.w - av.y);

            // best IoU as (inter, ua) pair; strict > keeps first-argmax tie semantics
            float bi = 0.f, bu = 1.f;
            int   bm = -1;
            #pragma unroll 4
            for (int m = 0; m < mlim; m++) {
                float4 gb = s_box[m];
                float2 gm = s_meta[m];
                float iw = fminf(av.z, gb.z) - fmaxf(av.x, gb.x);
                float ih = fminf(av.w, gb.w) - fmaxf(av.y, gb.y);
                float inter = fmaxf(iw, 0.f) * fmaxf(ih, 0.f);
                float ua = fmaxf(aarea + gm.x - inter, 1e-8f);
                if (inter * bu > bi * ua) { bi = inter; bu = ua; bm = m; }
            }

            bool pos = (bm >= 0) && (bi >= 0.5f * bu);
            bool neg = (bi < 0.4f * bu);
            w = (pos || neg) ? NEGK : 0.f;

            if (pos) {
                accP++;
                float4 gb = s_box[bm];
                float aw = av.z - av.x;
                float ah = av.w - av.y;
                float gwr = gb.z - gb.x, ghr = gb.w - gb.y;
                float acx = av.x + 0.5f * aw, acy = av.y + 0.5f * ah;
                float gcx = gb.x + 0.5f * gwr, gcy = gb.y + 0.5f * ghr;
                float gw = fmaxf(gwr, 1.f), gh = fmaxf(ghr, 1.f);
                float t0 = ((gcx - acx) / aw) / 0.1f;
                float t1 = ((gcy - acy) / ah) / 0.1f;
                float t2 = logf(gw / aw) / 0.2f;
                float t3 = logf(gh / ah) / 0.2f;
                float4 rv = __ldg(((const float4*)reg) + (size_t)b * A + a);
                float d0 = fabsf(t0 - rv.x);
                float d1 = fabsf(t1 - rv.y);
                float d2 = fabsf(t2 - rv.z);
                float d3 = fabsf(t3 - rv.w);
                const float TH = 1.0f / 9.0f;
                const float CC = 0.5f / 9.0f;
                accR += (d0 <= TH) ? 4.5f * d0 * d0 : d0 - CC;
                accR += (d1 <= TH) ? 4.5f * d1 * d1 : d1 - CC;
                accR += (d2 <= TH) ? 4.5f * d2 * d2 : d2 - CC;
                accR += (d3 <= TH) ? 4.5f * d3 * d3 : d3 - CC;

                // one-hot lane correction: streaming adds NEGK*c^2*lg2(1-c);
                // replace with the positive focal term.
                int lab = (int)s_meta[bm].y;
                float c = __ldg(cls + ((size_t)b * A + a) * K + lab);
                float u = 1.f - c;
                accC += POSK * u * u * __log2f(c) - NEGK * c * c * __log2f(u);
            }
        }
        s_w[tid] = w;
        __syncthreads();

        // ---- phase 2: packed-f32x2 coalesced streaming over [a0:a0+256, 0:K] ----
        int nA = A - a0; if (nA > TPB) nA = TPB;
        const float4* cb = (const float4*)(cls + ((size_t)b * A + (size_t)a0) * K);

        if (KT > 0 && nA == TPB) {
            constexpr int ITERS = (KT > 0) ? (KT / 4) : 1;
            #pragma unroll 5
            for (int j = 0; j < ITERS; j++) {
                int i = j * TPB + tid;
                float4 v = __ldcs(cb + i);
                float ww = s_w[i / K4];          // constexpr divisor -> umulhi+shr
                unsigned long long c01 = pk2(v.x, v.y);
                unsigned long long c23 = pk2(v.z, v.w);
                unsigned long long u01 = fma2(c01, NEG2, ONE2);   // (1-c) packed
                unsigned long long u23 = fma2(c23, NEG2, ONE2);
                float u0, u1, u2, u3;
                upk2(u01, u0, u1);
                upk2(u23, u2, u3);
                float l0 = __log2f(u0);
                float l1 = __log2f(u1);
                float l2 = __log2f(u2);
                float l3 = __log2f(u3);
                unsigned long long cc01 = mul2(c01, c01);         // c^2 packed
                unsigned long long cc23 = mul2(c23, c23);
                unsigned long long t01 = mul2(cc01, pk2(l0, l1)); // c^2 * lg2(1-c)
                unsigned long long t23 = mul2(cc23, pk2(l2, l3));
                unsigned long long sp = add2(t01, t23);
                float s0, s1;
                upk2(sp, s0, s1);
                accC = fmaf(ww, s0 + s1, accC);
            }
        } else {
            int total = nA * K4;
            for (int i = tid; i < total; i += TPB) {
                float4 v = __ldcs(cb + i);
                float ww = s_w[i / K4];
                float l0 = __log2f(1.f - v.x);
                float l1 = __log2f(1.f - v.y);
                float l2 = __log2f(1.f - v.z);
                float l3 = __log2f(1.f - v.w);
                float s = fmaf(v.x * v.x, l0,
                          fmaf(v.y * v.y, l1,
                          fmaf(v.z * v.z, l2, (v.w * v.w) * l3)));
                accC = fmaf(ww, s, accC);
            }
            int kRem = K - (K4 << 2);
            if (kRem) {
                for (int i = tid; i < nA * kRem; i += TPB) {
                    int aL = i / kRem;
                    int k  = (K4 << 2) + (i - aL * kRem);
                    float c = __ldg(cls + ((size_t)b * A + a0 + aL) * K + k);
                    accC = fmaf(s_w[aL], c * c * __log2f(1.f - c), accC);
                }
            }
        }
        __syncthreads();   // protect s_w before next tile rewrites it
    }

    // ---- block reduce & write per-block partials ----
    s_redC[tid] = accC;
    s_redR[tid] = accR;
    s_redP[tid] = accP;
    __syncthreads();
    for (int off = TPB / 2; off > 0; off >>= 1) {
        if (tid < off) {
            s_redC[tid] += s_redC[tid + off];
            s_redR[tid] += s_redR[tid + off];
            s_redP[tid] += s_redP[tid + off];
        }
        __syncthreads();
    }
    if (tid == 0) {
        g_partC[b * MAXBLK + blockIdx.x] = s_redC[0];
        g_partR[b * MAXBLK + blockIdx.x] = s_redR[0];
        g_partP[b * MAXBLK + blockIdx.x] = s_redP[0];
        __threadfence();
        unsigned v = atomicAdd(&g_done, 1u);
        s_isLast = (v == (unsigned)(nBlkTotal - 1));
    }
    __syncthreads();

    // ---- last block: fused finalize (one warp per image) ----
    if (s_isLast) {
        __threadfence();
        const int wrp  = tid >> 5;
        const int lane = tid & 31;
        const int nblk = gridDim.x;
        if (wrp < B) {
            float c = 0.f, r = 0.f; int p = 0;
            for (int i = lane; i < nblk; i += 32) {
                c += g_partC[wrp * MAXBLK + i];
                r += g_partR[wrp * MAXBLK + i];
                p += g_partP[wrp * MAXBLK + i];
            }
            #pragma unroll
            for (int off = 16; off > 0; off >>= 1) {
                c += __shfl_down_sync(0xffffffffu, c, off);
                r += __shfl_down_sync(0xffffffffu, r, off);
                p += __shfl_down_sync(0xffffffffu, p, off);
            }
            bool hv = false;
            for (int m = lane; m < M; m += 32)
                if (__ldg(ann + ((size_t)wrp * M + m) * 5 + 4) != -1.0f) hv = true;
            unsigned hvb = __ballot_sync(0xffffffffu, hv);
            if (lane == 0) {
                double cv = 0.0, rv = 0.0;
                if (hvb != 0u) cv = (double)c / (double)(p > 1 ? p : 1);
                if (p > 0) {
                    int d = p * 4 > 1 ? p * 4 : 1;
                    rv = (double)r / (double)d;
                }
                shC[wrp] = cv;
                shR[wrp] = rv;
            }
        }
        __syncthreads();
        if (tid == 0) {
            double cs = 0.0, rs = 0.0;
            for (int i = 0; i < B; i++) { cs += shC[i]; rs += shR[i]; }
            out[0] = (float)(cs / (double)B);
            out[1] = (float)(rs / (double)B);
            atomicExch(&g_done, 0u);   // reset for graph replay
        }
    }
}

extern "C" void kernel_launch(void* const* d_in, const int* in_sizes, int n_in,
                              void* d_out, int out_size) {
    const float* cls = (const float*)d_in[0];
    const float* reg = (const float*)d_in[1];
    const float* anc = (const float*)d_in[2];
    const float* ann = (const float*)d_in[3];

    int A = in_sizes[2] / 4;                                        // anchors [1,A,4]
    int B = in_sizes[1] / (A * 4);                                  // regressions [B,A,4]
    int K = (int)((long long)in_sizes[0] / ((long long)A * B));     // cls [B,A,K]
    int M = in_sizes[3] / (B * 5);                                  // annotations [B,M,5]

    int nTiles = (A + TPB - 1) / TPB;
    int gx0 = (148 * 6) / (B > 0 ? B : 1);      // round-6 grid: 6 blocks/SM target
    if (gx0 < 1) gx0 = 1;
    int tpb = (nTiles + gx0 - 1) / gx0;         // balanced tiles per block
    int gx  = (nTiles + tpb - 1) / tpb;
    if (gx > MAXBLK) gx = MAXBLK;
    if (gx < 1) gx = 1;
    dim3 grid(gx, B);

    if (K == 80)
        focal_main<80><<<grid, TPB>>>(cls, reg, anc, ann, A, K, M, nTiles, gx * B, (float*)d_out);
    else
        focal_main<0><<<grid, TPB>>>(cls, reg, anc, ann, A, K, M, nTiles, gx * B, (float*)d_out);
}